// round 1
// baseline (speedup 1.0000x reference)
#include <cuda_runtime.h>
#include <math.h>

// Problem constants
#define N_ROWS   384
#define BS       192
#define PD       16
#define DDIM     73728          // 32*48*48
#define INV_TEMP 10.0f
#define EPS      1e-6f

// GEMM tiling
#define BMT 64
#define BNT 64
#define BKT 32
#define NSPLIT 32
#define KCHUNK (DDIM / NSPLIT)  // 2304
#define NTILE  (N_ROWS / BMT)   // 6

// Device scratch (no cudaMalloc allowed)
static __device__ float g_Zn[(size_t)N_ROWS * DDIM];            // 113 MB normalized rows
static __device__ float g_part[(size_t)NSPLIT * N_ROWS * N_ROWS]; // split-K partials, 18.9 MB
static __device__ float g_S[N_ROWS * N_ROWS];                   // raw dot products
static __device__ float g_Dsum[N_ROWS];

__inline__ __device__ float blockReduceSum(float v) {
    __shared__ float sh[33];
    int lane = threadIdx.x & 31, w = threadIdx.x >> 5;
    #pragma unroll
    for (int o = 16; o; o >>= 1) v += __shfl_down_sync(0xffffffffu, v, o);
    if (lane == 0) sh[w] = v;
    __syncthreads();
    int nw = (blockDim.x + 31) >> 5;
    v = (threadIdx.x < nw) ? sh[lane] : 0.f;
    if (w == 0) {
        #pragma unroll
        for (int o = 16; o; o >>= 1) v += __shfl_down_sync(0xffffffffu, v, o);
        if (lane == 0) sh[32] = v;
    }
    __syncthreads();
    return sh[32];
}

// One block per row: demean, compute norm, write normalized row.
__global__ __launch_bounds__(256) void prep_kernel(const float* __restrict__ X,
                                                   const float* __restrict__ M) {
    int row = blockIdx.x;
    int ds = (row >> 2) & 3;  // (row / N_PARTS) % N_DATASETS
    const float4* x = (const float4*)(X + (size_t)row * DDIM);
    const float4* m = (const float4*)(M + (size_t)ds * DDIM);
    float ss = 0.f;
    for (int i = threadIdx.x; i < DDIM / 4; i += blockDim.x) {
        float4 xv = x[i], mv = m[i];
        float a = xv.x - mv.x, b = xv.y - mv.y, c = xv.z - mv.z, d = xv.w - mv.w;
        ss += a * a + b * b + c * c + d * d;
    }
    float tot = blockReduceSum(ss);
    float rn = 1.f / fmaxf(sqrtf(tot), EPS);
    float4* z = (float4*)(g_Zn + (size_t)row * DDIM);
    for (int i = threadIdx.x; i < DDIM / 4; i += blockDim.x) {
        float4 xv = x[i], mv = m[i];
        float4 o;
        o.x = (xv.x - mv.x) * rn; o.y = (xv.y - mv.y) * rn;
        o.z = (xv.z - mv.z) * rn; o.w = (xv.w - mv.w) * rn;
        z[i] = o;
    }
}

// Split-K fp32 tiled GEMM: S_part[split] = Zn[bm:bm+64] . Zn[bn:bn+64]^T over KCHUNK.
__global__ __launch_bounds__(256) void gemm_kernel() {
    __shared__ float As[BKT][BMT];
    __shared__ float Bs[BKT][BNT];
    const int bm = blockIdx.x * BMT;
    const int bn = blockIdx.y * BNT;
    const int k0 = blockIdx.z * KCHUNK;
    const int tid = threadIdx.x;
    const int tx = tid & 15;   // col group
    const int ty = tid >> 4;   // row group
    float acc[4][4] = {};

    for (int kt = 0; kt < KCHUNK; kt += BKT) {
        const int kbase = k0 + kt;
        #pragma unroll
        for (int l = 0; l < 2; l++) {
            int idx = tid + l * 256;      // 0..511
            int row = idx >> 3;           // 0..63
            int kc4 = idx & 7;            // float4 slot in BK
            float4 va = *(const float4*)(g_Zn + (size_t)(bm + row) * DDIM + kbase + kc4 * 4);
            As[kc4 * 4 + 0][row] = va.x; As[kc4 * 4 + 1][row] = va.y;
            As[kc4 * 4 + 2][row] = va.z; As[kc4 * 4 + 3][row] = va.w;
            float4 vb = *(const float4*)(g_Zn + (size_t)(bn + row) * DDIM + kbase + kc4 * 4);
            Bs[kc4 * 4 + 0][row] = vb.x; Bs[kc4 * 4 + 1][row] = vb.y;
            Bs[kc4 * 4 + 2][row] = vb.z; Bs[kc4 * 4 + 3][row] = vb.w;
        }
        __syncthreads();
        #pragma unroll
        for (int kk = 0; kk < BKT; kk++) {
            float4 a4 = *(const float4*)&As[kk][ty * 4];
            float4 b4 = *(const float4*)&Bs[kk][tx * 4];
            float a[4] = {a4.x, a4.y, a4.z, a4.w};
            float b[4] = {b4.x, b4.y, b4.z, b4.w};
            #pragma unroll
            for (int mi = 0; mi < 4; mi++)
                #pragma unroll
                for (int ni = 0; ni < 4; ni++)
                    acc[mi][ni] += a[mi] * b[ni];
        }
        __syncthreads();
    }

    float* out = g_part + (size_t)blockIdx.z * N_ROWS * N_ROWS;
    #pragma unroll
    for (int mi = 0; mi < 4; mi++)
        #pragma unroll
        for (int ni = 0; ni < 4; ni++)
            out[(size_t)(bm + ty * 4 + mi) * N_ROWS + (bn + tx * 4 + ni)] = acc[mi][ni];
}

// Deterministic reduction of split-K partials.
__global__ __launch_bounds__(256) void reduce_kernel() {
    int i = blockIdx.x * blockDim.x + threadIdx.x;
    if (i >= N_ROWS * N_ROWS) return;
    float s = 0.f;
    #pragma unroll
    for (int sp = 0; sp < NSPLIT; sp++)
        s += g_part[(size_t)sp * N_ROWS * N_ROWS + i];
    g_S[i] = s;
}

// Dsum[a] = sum_{j: j%PD != a%PD} exp(S[a][j] * INV_TEMP)
__global__ __launch_bounds__(128) void dsum_kernel() {
    int a = blockIdx.x;
    int ra = a % PD;
    float s = 0.f;
    for (int j = threadIdx.x; j < N_ROWS; j += blockDim.x) {
        if ((j % PD) != ra)
            s += expf(g_S[a * N_ROWS + j] * INV_TEMP);
    }
    float tot = blockReduceSum(s);
    if (threadIdx.x == 0) g_Dsum[a] = tot;
}

__inline__ __device__ float pair_loss(int a, int b) {
    float num = g_S[a * N_ROWS + b] * INV_TEMP;
    float en = expf(num);
    return -(num - logf(en + g_Dsum[a])) - (num - logf(en + g_Dsum[b]));
}

__global__ __launch_bounds__(256) void loss_kernel(float* __restrict__ out) {
    int p = threadIdx.x;
    float l = 0.f;
    if (p < BS) {
        int i1 = p;
        int i2 = BS + p;
        int i3 = (p + PD) % N_ROWS;
        int i4 = (BS + p + PD) % N_ROWS;
        l = pair_loss(i1, i2) + pair_loss(i3, i4)
          + pair_loss(i1, i3) + pair_loss(i2, i4);
    }
    float tot = blockReduceSum(l);
    if (threadIdx.x == 0) out[0] = tot / 576.0f;  // N_TRANSFORMS * 3 * BS
}

extern "C" void kernel_launch(void* const* d_in, const int* in_sizes, int n_in,
                              void* d_out, int out_size) {
    const float* reg_pred = (const float*)d_in[0];
    const float* means    = (const float*)d_in[1];
    // Defensive: identify inputs by size (reg_pred has 384*73728, means 4*73728)
    if (n_in >= 2 && in_sizes[0] < in_sizes[1]) {
        reg_pred = (const float*)d_in[1];
        means    = (const float*)d_in[0];
    }
    float* out = (float*)d_out;

    prep_kernel<<<N_ROWS, 256>>>(reg_pred, means);
    dim3 g(NTILE, NTILE, NSPLIT);
    gemm_kernel<<<g, 256>>>();
    reduce_kernel<<<(N_ROWS * N_ROWS + 255) / 256, 256>>>();
    dsum_kernel<<<N_ROWS, 128>>>();
    loss_kernel<<<1, 256>>>(out);
}

// round 3
// speedup vs baseline: 4.8052x; 4.8052x over previous
#include <cuda_runtime.h>
#include <cuda_bf16.h>
#include <cstdint>
#include <cstddef>
#include <math.h>

// Problem constants
#define N_ROWS   384
#define BS       192
#define PD       16
#define DDIM     73728          // 32*48*48
#define INV_TEMP 10.0f
#define EPS      1e-6f

// GEMM tiling (bf16 tensor cores)
#define BM 128
#define BN 128
#define BK 64
#define NSPLIT 24
#define KCHUNK (DDIM / NSPLIT)  // 3072
#define NTILES 6                // upper-tri 3x3 of 128-tiles
#define SROW 72                 // padded smem row (bf16 elems): 144B stride, conflict-free ldmatrix

// Device scratch (no cudaMalloc allowed)
static __device__ __nv_bfloat16 g_Znh[(size_t)N_ROWS * DDIM];       // 56.6 MB unnormalized bf16 Z
static __device__ float g_rn[N_ROWS];                               // 1/norm per row
static __device__ float g_part[(size_t)NSPLIT * NTILES * BM * BN];  // split-K partials 9.4 MB
static __device__ float g_S[N_ROWS * N_ROWS];
static __device__ float g_Dsum[N_ROWS];

__inline__ __device__ float blockReduceSum(float v) {
    __shared__ float sh[33];
    int lane = threadIdx.x & 31, w = threadIdx.x >> 5;
    #pragma unroll
    for (int o = 16; o; o >>= 1) v += __shfl_down_sync(0xffffffffu, v, o);
    if (lane == 0) sh[w] = v;
    __syncthreads();
    int nw = (blockDim.x + 31) >> 5;
    v = (threadIdx.x < nw) ? sh[lane] : 0.f;
    if (w == 0) {
        #pragma unroll
        for (int o = 16; o; o >>= 1) v += __shfl_down_sync(0xffffffffu, v, o);
        if (lane == 0) sh[32] = v;
    }
    __syncthreads();
    return sh[32];
}

// Single pass: demean, round to bf16, write; accumulate sum of squares of the
// ROUNDED values (so norms match the bf16 data fed to the GEMM exactly).
__global__ __launch_bounds__(256) void prep_kernel(const float* __restrict__ X,
                                                   const float* __restrict__ M) {
    int row = blockIdx.x;
    int ds = (row >> 2) & 3;  // (row / N_PARTS) % N_DATASETS
    const float4* x = (const float4*)(X + (size_t)row * DDIM);
    const float4* m = (const float4*)(M + (size_t)ds * DDIM);
    uint4* z = (uint4*)(g_Znh + (size_t)row * DDIM);
    float ss = 0.f;
    for (int i = threadIdx.x; i < DDIM / 8; i += blockDim.x) {
        float4 x0 = x[2 * i], x1 = x[2 * i + 1];
        float4 m0 = m[2 * i], m1 = m[2 * i + 1];
        __nv_bfloat162 h0 = __floats2bfloat162_rn(x0.x - m0.x, x0.y - m0.y);
        __nv_bfloat162 h1 = __floats2bfloat162_rn(x0.z - m0.z, x0.w - m0.w);
        __nv_bfloat162 h2 = __floats2bfloat162_rn(x1.x - m1.x, x1.y - m1.y);
        __nv_bfloat162 h3 = __floats2bfloat162_rn(x1.z - m1.z, x1.w - m1.w);
        uint4 o;
        o.x = *(const unsigned int*)&h0; o.y = *(const unsigned int*)&h1;
        o.z = *(const unsigned int*)&h2; o.w = *(const unsigned int*)&h3;
        z[i] = o;
        float2 f0 = __bfloat1622float2(h0), f1 = __bfloat1622float2(h1);
        float2 f2 = __bfloat1622float2(h2), f3 = __bfloat1622float2(h3);
        ss += f0.x * f0.x + f0.y * f0.y + f1.x * f1.x + f1.y * f1.y
            + f2.x * f2.x + f2.y * f2.y + f3.x * f3.x + f3.y * f3.y;
    }
    float tot = blockReduceSum(ss);
    if (threadIdx.x == 0) g_rn[row] = 1.f / fmaxf(sqrtf(tot), EPS);
}

__device__ __forceinline__ void ldsm_x4(uint32_t addr, uint32_t& r0, uint32_t& r1,
                                        uint32_t& r2, uint32_t& r3) {
    asm volatile("ldmatrix.sync.aligned.m8n8.x4.shared.b16 {%0,%1,%2,%3}, [%4];"
                 : "=r"(r0), "=r"(r1), "=r"(r2), "=r"(r3) : "r"(addr));
}
__device__ __forceinline__ void ldsm_x2(uint32_t addr, uint32_t& r0, uint32_t& r1) {
    asm volatile("ldmatrix.sync.aligned.m8n8.x2.shared.b16 {%0,%1}, [%2];"
                 : "=r"(r0), "=r"(r1) : "r"(addr));
}
__device__ __forceinline__ void mma16816(float* c, const uint32_t* a, const uint32_t* b) {
    asm volatile("mma.sync.aligned.m16n8k16.row.col.f32.bf16.bf16.f32 "
                 "{%0,%1,%2,%3}, {%4,%5,%6,%7}, {%8,%9}, {%0,%1,%2,%3};"
                 : "+f"(c[0]), "+f"(c[1]), "+f"(c[2]), "+f"(c[3])
                 : "r"(a[0]), "r"(a[1]), "r"(a[2]), "r"(a[3]), "r"(b[0]), "r"(b[1]));
}

// Upper-tri split-K bf16 Gram GEMM: 128x128 tiles, 8 warps, warp tile 64x32.
__global__ __launch_bounds__(256) void gemm_bf16_kernel() {
    __shared__ __nv_bfloat16 As[BM * SROW];
    __shared__ __nv_bfloat16 Bs[BN * SROW];
    static const int TI[NTILES] = {0, 0, 0, 1, 1, 2};
    static const int TJ[NTILES] = {0, 1, 2, 1, 2, 2};
    const int tp = blockIdx.x;          // 0..5
    const int split = blockIdx.y;       // 0..23
    const int bm = TI[tp] * BM, bn = TJ[tp] * BN;
    const int k0 = split * KCHUNK;
    const int tid = threadIdx.x, wid = tid >> 5, lane = tid & 31;
    const int wm = (wid >> 2) * 64, wn = (wid & 3) * 32;

    float acc[4][4][4] = {};

    #pragma unroll 1
    for (int kt = 0; kt < KCHUNK; kt += BK) {
        const int kb = k0 + kt;
        #pragma unroll
        for (int l = 0; l < 4; l++) {
            int idx = tid + l * 256;        // 0..1023
            int row = idx >> 3;             // 0..127
            int c16 = idx & 7;              // 16B chunk within BK
            *(uint4*)(As + row * SROW + c16 * 8) =
                *(const uint4*)(g_Znh + (size_t)(bm + row) * DDIM + kb + c16 * 8);
            *(uint4*)(Bs + row * SROW + c16 * 8) =
                *(const uint4*)(g_Znh + (size_t)(bn + row) * DDIM + kb + c16 * 8);
        }
        __syncthreads();
        #pragma unroll
        for (int ks = 0; ks < 4; ks++) {
            uint32_t a[4][4], b[4][2];
            #pragma unroll
            for (int mi = 0; mi < 4; mi++) {
                int r = wm + mi * 16 + (lane & 15);
                int cc = ks * 16 + (lane >> 4) * 8;
                uint32_t addr = (uint32_t)__cvta_generic_to_shared(As + r * SROW + cc);
                ldsm_x4(addr, a[mi][0], a[mi][1], a[mi][2], a[mi][3]);
            }
            #pragma unroll
            for (int ni = 0; ni < 4; ni++) {
                int r = wn + ni * 8 + (lane & 7);
                int cc = ks * 16 + ((lane >> 3) & 1) * 8;
                uint32_t addr = (uint32_t)__cvta_generic_to_shared(Bs + r * SROW + cc);
                ldsm_x2(addr, b[ni][0], b[ni][1]);
            }
            #pragma unroll
            for (int mi = 0; mi < 4; mi++)
                #pragma unroll
                for (int ni = 0; ni < 4; ni++)
                    mma16816(acc[mi][ni], a[mi], b[ni]);
        }
        __syncthreads();
    }

    float* out = g_part + ((size_t)split * NTILES + tp) * (BM * BN);
    #pragma unroll
    for (int mi = 0; mi < 4; mi++) {
        #pragma unroll
        for (int ni = 0; ni < 4; ni++) {
            int r0 = wm + mi * 16 + (lane >> 2);
            int c0 = wn + ni * 8 + 2 * (lane & 3);
            *(float2*)&out[r0 * BN + c0]       = make_float2(acc[mi][ni][0], acc[mi][ni][1]);
            *(float2*)&out[(r0 + 8) * BN + c0] = make_float2(acc[mi][ni][2], acc[mi][ni][3]);
        }
    }
}

// Deterministic split-K reduce + mirror (S symmetric) + normalization scale.
__global__ __launch_bounds__(256) void reduce_kernel() {
    int i = blockIdx.x * blockDim.x + threadIdx.x;
    if (i >= N_ROWS * N_ROWS) return;
    int a = i / N_ROWS, b = i - a * N_ROWS;
    int ti = a >> 7, tj = b >> 7;
    int r, c, t0, t1;
    if (ti <= tj) { t0 = ti; t1 = tj; r = a & 127; c = b & 127; }
    else          { t0 = tj; t1 = ti; r = b & 127; c = a & 127; }
    int tp = (t0 == 0) ? t1 : (t0 == 1 ? 2 + t1 : 3 + t1);
    float s = 0.f;
    #pragma unroll
    for (int sp = 0; sp < NSPLIT; sp++)
        s += g_part[((size_t)sp * NTILES + tp) * (BM * BN) + r * BN + c];
    g_S[i] = s * g_rn[a] * g_rn[b];
}

// Dsum[a] = sum_{j: j%PD != a%PD} exp(S[a][j] * INV_TEMP)
__global__ __launch_bounds__(128) void dsum_kernel() {
    int a = blockIdx.x;
    int ra = a % PD;
    float s = 0.f;
    for (int j = threadIdx.x; j < N_ROWS; j += blockDim.x) {
        if ((j % PD) != ra)
            s += expf(g_S[a * N_ROWS + j] * INV_TEMP);
    }
    float tot = blockReduceSum(s);
    if (threadIdx.x == 0) g_Dsum[a] = tot;
}

__inline__ __device__ float pair_loss(int a, int b) {
    float num = g_S[a * N_ROWS + b] * INV_TEMP;
    float en = expf(num);
    return -(num - logf(en + g_Dsum[a])) - (num - logf(en + g_Dsum[b]));
}

__global__ __launch_bounds__(256) void loss_kernel(float* __restrict__ out) {
    int p = threadIdx.x;
    float l = 0.f;
    if (p < BS) {
        int i1 = p;
        int i2 = BS + p;
        int i3 = (p + PD) % N_ROWS;
        int i4 = (BS + p + PD) % N_ROWS;
        l = pair_loss(i1, i2) + pair_loss(i3, i4)
          + pair_loss(i1, i3) + pair_loss(i2, i4);
    }
    float tot = blockReduceSum(l);
    if (threadIdx.x == 0) out[0] = tot / 576.0f;  // N_TRANSFORMS * 3 * BS
}

extern "C" void kernel_launch(void* const* d_in, const int* in_sizes, int n_in,
                              void* d_out, int out_size) {
    const float* reg_pred = (const float*)d_in[0];
    const float* means    = (const float*)d_in[1];
    if (n_in >= 2 && in_sizes[0] < in_sizes[1]) {
        reg_pred = (const float*)d_in[1];
        means    = (const float*)d_in[0];
    }
    float* out = (float*)d_out;

    prep_kernel<<<N_ROWS, 256>>>(reg_pred, means);
    dim3 g(NTILES, NSPLIT);
    gemm_bf16_kernel<<<g, 256>>>();
    reduce_kernel<<<(N_ROWS * N_ROWS + 255) / 256, 256>>>();
    dsum_kernel<<<N_ROWS, 128>>>();
    loss_kernel<<<1, 256>>>(out);
}

// round 6
// speedup vs baseline: 8.8437x; 1.8404x over previous
#include <cuda_runtime.h>
#include <cuda_bf16.h>
#include <cstdint>
#include <cstddef>
#include <math.h>

// Problem constants
#define N_ROWS   384
#define BS       192
#define PD       16
#define DDIM     73728          // 32*48*48
#define INV_TEMP 10.0f
#define EPS      1e-6f

// GEMM tiling (bf16 tensor cores)
#define BM 128
#define BN 128
#define BK 64
#define STAGES 4
#define NSPLIT 24
#define KCHUNK (DDIM / NSPLIT)  // 3072
#define NIT (KCHUNK / BK)       // 48
#define NTILES 6                // upper-tri 3x3 of 128-tiles
#define SROW 72                 // padded smem row (bf16): 144B stride, 16B-aligned, conflict-free
#define STAGE_ELEMS (BM * SROW)
#define SMEM_BYTES (STAGES * 2 * STAGE_ELEMS * (int)sizeof(__nv_bfloat16))

// Device scratch (no cudaMalloc allowed)
static __device__ __nv_bfloat16 g_Znh[(size_t)N_ROWS * DDIM];       // 56.6 MB bf16 Z (unnormalized)
static __device__ float g_rn[N_ROWS];
static __device__ float g_part[(size_t)NSPLIT * NTILES * BM * BN];  // split-K partials 9.4 MB
static __device__ float g_S[N_ROWS * N_ROWS];
static __device__ float g_Dsum[N_ROWS];

__inline__ __device__ float blockReduceSum(float v) {
    __shared__ float sh[33];
    int lane = threadIdx.x & 31, w = threadIdx.x >> 5;
    #pragma unroll
    for (int o = 16; o; o >>= 1) v += __shfl_down_sync(0xffffffffu, v, o);
    if (lane == 0) sh[w] = v;
    __syncthreads();
    int nw = (blockDim.x + 31) >> 5;
    v = (threadIdx.x < nw) ? sh[lane] : 0.f;
    if (w == 0) {
        #pragma unroll
        for (int o = 16; o; o >>= 1) v += __shfl_down_sync(0xffffffffu, v, o);
        if (lane == 0) sh[32] = v;
    }
    __syncthreads();
    return sh[32];
}

// Demean, round to bf16, write; norm from the ROUNDED values (consistent with GEMM).
__global__ __launch_bounds__(256) void prep_kernel(const float* __restrict__ X,
                                                   const float* __restrict__ M) {
    int row = blockIdx.x;
    int ds = (row >> 2) & 3;
    const float4* x = (const float4*)(X + (size_t)row * DDIM);
    const float4* m = (const float4*)(M + (size_t)ds * DDIM);
    uint4* z = (uint4*)(g_Znh + (size_t)row * DDIM);
    float ss = 0.f;
    for (int i = threadIdx.x; i < DDIM / 8; i += blockDim.x) {
        float4 x0 = x[2 * i], x1 = x[2 * i + 1];
        float4 m0 = m[2 * i], m1 = m[2 * i + 1];
        __nv_bfloat162 h0 = __floats2bfloat162_rn(x0.x - m0.x, x0.y - m0.y);
        __nv_bfloat162 h1 = __floats2bfloat162_rn(x0.z - m0.z, x0.w - m0.w);
        __nv_bfloat162 h2 = __floats2bfloat162_rn(x1.x - m1.x, x1.y - m1.y);
        __nv_bfloat162 h3 = __floats2bfloat162_rn(x1.z - m1.z, x1.w - m1.w);
        uint4 o;
        o.x = *(const unsigned int*)&h0; o.y = *(const unsigned int*)&h1;
        o.z = *(const unsigned int*)&h2; o.w = *(const unsigned int*)&h3;
        z[i] = o;
        float2 f0 = __bfloat1622float2(h0), f1 = __bfloat1622float2(h1);
        float2 f2 = __bfloat1622float2(h2), f3 = __bfloat1622float2(h3);
        ss += f0.x * f0.x + f0.y * f0.y + f1.x * f1.x + f1.y * f1.y
            + f2.x * f2.x + f2.y * f2.y + f3.x * f3.x + f3.y * f3.y;
    }
    float tot = blockReduceSum(ss);
    if (threadIdx.x == 0) g_rn[row] = 1.f / fmaxf(sqrtf(tot), EPS);
}

__device__ __forceinline__ void ldsm_x4(uint32_t addr, uint32_t& r0, uint32_t& r1,
                                        uint32_t& r2, uint32_t& r3) {
    asm volatile("ldmatrix.sync.aligned.m8n8.x4.shared.b16 {%0,%1,%2,%3}, [%4];"
                 : "=r"(r0), "=r"(r1), "=r"(r2), "=r"(r3) : "r"(addr));
}
__device__ __forceinline__ void ldsm_x2(uint32_t addr, uint32_t& r0, uint32_t& r1) {
    asm volatile("ldmatrix.sync.aligned.m8n8.x2.shared.b16 {%0,%1}, [%2];"
                 : "=r"(r0), "=r"(r1) : "r"(addr));
}
__device__ __forceinline__ void mma16816(float* c, const uint32_t* a, const uint32_t* b) {
    asm volatile("mma.sync.aligned.m16n8k16.row.col.f32.bf16.bf16.f32 "
                 "{%0,%1,%2,%3}, {%4,%5,%6,%7}, {%8,%9}, {%0,%1,%2,%3};"
                 : "+f"(c[0]), "+f"(c[1]), "+f"(c[2]), "+f"(c[3])
                 : "r"(a[0]), "r"(a[1]), "r"(a[2]), "r"(a[3]), "r"(b[0]), "r"(b[1]));
}
__device__ __forceinline__ void cp16(void* smem, const void* g) {
    uint32_t s = (uint32_t)__cvta_generic_to_shared(smem);
    asm volatile("cp.async.ca.shared.global [%0], [%1], 16;" :: "r"(s), "l"(g));
}
__device__ __forceinline__ void cp_commit() {
    asm volatile("cp.async.commit_group;");
}

// Upper-tri split-K bf16 Gram GEMM, cp.async 4-stage pipeline.
__global__ __launch_bounds__(256) void gemm_bf16_kernel() {
    extern __shared__ __nv_bfloat16 smem[];
    __nv_bfloat16* As = smem;                            // [STAGES][BM*SROW]
    __nv_bfloat16* Bs = smem + STAGES * STAGE_ELEMS;     // [STAGES][BM*SROW]
    static const int TI[NTILES] = {0, 0, 0, 1, 1, 2};
    static const int TJ[NTILES] = {0, 1, 2, 1, 2, 2};
    const int tp = blockIdx.x;
    const int split = blockIdx.y;
    const int bm = TI[tp] * BM, bn = TJ[tp] * BN;
    const int k0 = split * KCHUNK;
    const int tid = threadIdx.x, wid = tid >> 5, lane = tid & 31;
    const int wm = (wid >> 2) * 64, wn = (wid & 3) * 32;

    // per-thread fixed load slot: 4 rows x 1 chunk each matrix per stage
    const int lrow = tid >> 3;          // 0..31 base row group
    const int lc16 = tid & 7;           // 16B chunk

    float acc[4][4][4] = {};

    auto load_stage = [&](int it, int buf) {
        const int kb = k0 + it * BK;
        __nv_bfloat16* a = As + buf * STAGE_ELEMS;
        __nv_bfloat16* b = Bs + buf * STAGE_ELEMS;
        #pragma unroll
        for (int l = 0; l < 4; l++) {
            int row = lrow + l * 32;
            cp16(a + row * SROW + lc16 * 8,
                 g_Znh + (size_t)(bm + row) * DDIM + kb + lc16 * 8);
            cp16(b + row * SROW + lc16 * 8,
                 g_Znh + (size_t)(bn + row) * DDIM + kb + lc16 * 8);
        }
        cp_commit();
    };

    #pragma unroll
    for (int s = 0; s < STAGES - 1; s++) load_stage(s, s);

    #pragma unroll 1
    for (int it = 0; it < NIT; it++) {
        const int buf = it % STAGES;
        asm volatile("cp.async.wait_group %0;" :: "n"(STAGES - 2));
        __syncthreads();
        if (it + STAGES - 1 < NIT) load_stage(it + STAGES - 1, (it + STAGES - 1) % STAGES);

        const __nv_bfloat16* a_s = As + buf * STAGE_ELEMS;
        const __nv_bfloat16* b_s = Bs + buf * STAGE_ELEMS;
        #pragma unroll
        for (int ks = 0; ks < 4; ks++) {
            uint32_t a[4][4], b[4][2];
            #pragma unroll
            for (int mi = 0; mi < 4; mi++) {
                int r = wm + mi * 16 + (lane & 15);
                int cc = ks * 16 + (lane >> 4) * 8;
                uint32_t addr = (uint32_t)__cvta_generic_to_shared(a_s + r * SROW + cc);
                ldsm_x4(addr, a[mi][0], a[mi][1], a[mi][2], a[mi][3]);
            }
            #pragma unroll
            for (int ni = 0; ni < 4; ni++) {
                int r = wn + ni * 8 + (lane & 7);
                int cc = ks * 16 + ((lane >> 3) & 1) * 8;
                uint32_t addr = (uint32_t)__cvta_generic_to_shared(b_s + r * SROW + cc);
                ldsm_x2(addr, b[ni][0], b[ni][1]);
            }
            #pragma unroll
            for (int mi = 0; mi < 4; mi++)
                #pragma unroll
                for (int ni = 0; ni < 4; ni++)
                    mma16816(acc[mi][ni], a[mi], b[ni]);
        }
    }

    float* out = g_part + ((size_t)split * NTILES + tp) * (BM * BN);
    #pragma unroll
    for (int mi = 0; mi < 4; mi++) {
        #pragma unroll
        for (int ni = 0; ni < 4; ni++) {
            int r0 = wm + mi * 16 + (lane >> 2);
            int c0 = wn + ni * 8 + 2 * (lane & 3);
            *(float2*)&out[r0 * BN + c0]       = make_float2(acc[mi][ni][0], acc[mi][ni][1]);
            *(float2*)&out[(r0 + 8) * BN + c0] = make_float2(acc[mi][ni][2], acc[mi][ni][3]);
        }
    }
}

// One block per row a: reduce split-K partials (mirrored from upper-tri tiles),
// scale by rn[a]*rn[j], write S row, and accumulate masked exp -> Dsum[a].
__global__ __launch_bounds__(256) void reduce_dsum_kernel() {
    int a = blockIdx.x;
    int ra = a & 15;   // a % PD
    int ti = a >> 7;
    int ar = a & 127;
    float local = 0.f;
    for (int j = threadIdx.x; j < N_ROWS; j += blockDim.x) {
        int tj = j >> 7, jr = j & 127;
        int t0, t1, r, c;
        if (ti <= tj) { t0 = ti; t1 = tj; r = ar; c = jr; }
        else          { t0 = tj; t1 = ti; r = jr; c = ar; }
        int tp = (t0 == 0) ? t1 : (t0 == 1 ? 2 + t1 : 3 + t1);
        float s = 0.f;
        #pragma unroll
        for (int sp = 0; sp < NSPLIT; sp++)
            s += g_part[((size_t)sp * NTILES + tp) * (BM * BN) + r * BN + c];
        s *= g_rn[a] * g_rn[j];
        g_S[a * N_ROWS + j] = s;
        if ((j & 15) != ra) local += expf(s * INV_TEMP);
    }
    float tot = blockReduceSum(local);
    if (threadIdx.x == 0) g_Dsum[a] = tot;
}

__inline__ __device__ float pair_loss(int a, int b) {
    float num = g_S[a * N_ROWS + b] * INV_TEMP;
    float en = expf(num);
    return -(num - logf(en + g_Dsum[a])) - (num - logf(en + g_Dsum[b]));
}

__global__ __launch_bounds__(256) void loss_kernel(float* __restrict__ out) {
    int p = threadIdx.x;
    float l = 0.f;
    if (p < BS) {
        int i1 = p;
        int i2 = BS + p;
        int i3 = (p + PD) % N_ROWS;
        int i4 = (BS + p + PD) % N_ROWS;
        l = pair_loss(i1, i2) + pair_loss(i3, i4)
          + pair_loss(i1, i3) + pair_loss(i2, i4);
    }
    float tot = blockReduceSum(l);
    if (threadIdx.x == 0) out[0] = tot / 576.0f;  // N_TRANSFORMS * 3 * BS
}

extern "C" void kernel_launch(void* const* d_in, const int* in_sizes, int n_in,
                              void* d_out, int out_size) {
    const float* reg_pred = (const float*)d_in[0];
    const float* means    = (const float*)d_in[1];
    if (n_in >= 2 && in_sizes[0] < in_sizes[1]) {
        reg_pred = (const float*)d_in[1];
        means    = (const float*)d_in[0];
    }
    float* out = (float*)d_out;

    cudaFuncSetAttribute(gemm_bf16_kernel,
                         cudaFuncAttributeMaxDynamicSharedMemorySize, SMEM_BYTES);

    prep_kernel<<<N_ROWS, 256>>>(reg_pred, means);
    dim3 g(NTILES, NSPLIT);
    gemm_bf16_kernel<<<g, 256, SMEM_BYTES>>>();
    reduce_dsum_kernel<<<N_ROWS, 256>>>();
    loss_kernel<<<1, 256>>>(out);
}